// round 6
// baseline (speedup 1.0000x reference)
#include <cuda_runtime.h>
#include <math.h>

static constexpr int G = 256;
static constexpr int C = 256;
static constexpr int DSLOTS = G + G * C;   // 65792
static constexpr int MAXB = 8192;

__device__ float g_partial[MAXB];

// One warp per row. Each lane loads 8 root floats + 8 group floats (float4 x2 each),
// warp-shuffle logsumexp for both segments, lane 0 writes per-row loss.
__global__ void __launch_bounds__(256) hsm_row_kernel(
    const float* __restrict__ pred,
    const int* __restrict__ tgt,       // int32: JAX demotes int64 targets
    int Bn)
{
    const int warp = (blockIdx.x * blockDim.x + threadIdx.x) >> 5;
    const int lane = threadIdx.x & 31;
    if (warp >= Bn) return;

    const float* row = pred + (size_t)warp * DSLOTS;
    int t = tgt[warp];
    int group = t >> 8;            // t / 256
    int child = t & 255;           // t % 256
    group = min(max(group, 0), G - 1);   // defensive clamp (free if dtype correct)

    const float* grp = row + G + group * C;

    // 256 floats per segment = 64 float4; lane reads [lane] and [lane+32].
    const float4* r4 = reinterpret_cast<const float4*>(row);
    const float4* g4 = reinterpret_cast<const float4*>(grp);
    const float4 ra = r4[lane], rb = r4[lane + 32];
    const float4 ga = g4[lane], gb = g4[lane + 32];

    float mr = fmaxf(fmaxf(fmaxf(ra.x, ra.y), fmaxf(ra.z, ra.w)),
                     fmaxf(fmaxf(rb.x, rb.y), fmaxf(rb.z, rb.w)));
    float mg = fmaxf(fmaxf(fmaxf(ga.x, ga.y), fmaxf(ga.z, ga.w)),
                     fmaxf(fmaxf(gb.x, gb.y), fmaxf(gb.z, gb.w)));
    #pragma unroll
    for (int o = 16; o > 0; o >>= 1) {
        mr = fmaxf(mr, __shfl_xor_sync(0xffffffffu, mr, o));
        mg = fmaxf(mg, __shfl_xor_sync(0xffffffffu, mg, o));
    }

    float sr = expf(ra.x - mr) + expf(ra.y - mr) + expf(ra.z - mr) + expf(ra.w - mr)
             + expf(rb.x - mr) + expf(rb.y - mr) + expf(rb.z - mr) + expf(rb.w - mr);
    float sg = expf(ga.x - mg) + expf(ga.y - mg) + expf(ga.z - mg) + expf(ga.w - mg)
             + expf(gb.x - mg) + expf(gb.y - mg) + expf(gb.z - mg) + expf(gb.w - mg);
    #pragma unroll
    for (int o = 16; o > 0; o >>= 1) {
        sr += __shfl_xor_sync(0xffffffffu, sr, o);
        sg += __shfl_xor_sync(0xffffffffu, sg, o);
    }

    if (lane == 0) {
        const float xr = __ldg(row + group);
        const float xg = __ldg(grp + child);
        g_partial[warp] = (mr + logf(sr) - xr) + (mg + logf(sg) - xg);
    }
}

// Deterministic single-block reduction -> mean.
__global__ void __launch_bounds__(256) hsm_reduce_kernel(float* __restrict__ out, int Bn)
{
    __shared__ float sh[256];
    float s = 0.0f;
    for (int i = threadIdx.x; i < Bn; i += 256) s += g_partial[i];
    sh[threadIdx.x] = s;
    __syncthreads();
    #pragma unroll
    for (int o = 128; o > 0; o >>= 1) {
        if (threadIdx.x < o) sh[threadIdx.x] += sh[threadIdx.x + o];
        __syncthreads();
    }
    if (threadIdx.x == 0) out[0] = sh[0] / (float)Bn;
}

extern "C" void kernel_launch(void* const* d_in, const int* in_sizes, int n_in,
                              void* d_out, int out_size)
{
    const float* pred = (const float*)d_in[0];
    const int* tgt = (const int*)d_in[1];
    int Bn = in_sizes[1];             // number of rows (targets count)
    if (Bn > MAXB) Bn = MAXB;

    const int grid = (Bn + 7) / 8;    // 8 warps (rows) per 256-thread block

    hsm_row_kernel<<<grid, 256>>>(pred, tgt, Bn);
    hsm_reduce_kernel<<<1, 256>>>((float*)d_out, Bn);
}

// round 7
// speedup vs baseline: 1.0295x; 1.0295x over previous
#include <cuda_runtime.h>
#include <math.h>

static constexpr int G = 256;
static constexpr int C = 256;
static constexpr int DSLOTS = G + G * C;   // 65792
static constexpr int MAXBLOCKS = 1024;

__device__ float g_blockpart[MAXBLOCKS];
__device__ unsigned g_count = 0;           // self-resetting via atomicInc wrap

// One warp per row; 8 rows per 256-thread block. Fused grid reduction:
// last block to finish sums all block partials and writes the mean.
__global__ void __launch_bounds__(256) hsm_fused_kernel(
    const float* __restrict__ pred,
    const int* __restrict__ tgt,
    float* __restrict__ out,
    int Bn, int nblocks)
{
    __shared__ float sh_warp[8];
    __shared__ bool sh_last;

    const int lane = threadIdx.x & 31;
    const int wid  = threadIdx.x >> 5;
    const int row_id = blockIdx.x * 8 + wid;

    float loss = 0.0f;
    if (row_id < Bn) {
        const float* row = pred + (size_t)row_id * DSLOTS;
        const int t = tgt[row_id];
        int group = (t >> 8) & 255;
        const int child = t & 255;
        const float* grp = row + G + group * C;

        const float4* r4 = reinterpret_cast<const float4*>(row);
        const float4* g4 = reinterpret_cast<const float4*>(grp);
        const float4 ra = r4[lane], rb = r4[lane + 32];
        const float4 ga = g4[lane], gb = g4[lane + 32];

        float mr = fmaxf(fmaxf(fmaxf(ra.x, ra.y), fmaxf(ra.z, ra.w)),
                         fmaxf(fmaxf(rb.x, rb.y), fmaxf(rb.z, rb.w)));
        float mg = fmaxf(fmaxf(fmaxf(ga.x, ga.y), fmaxf(ga.z, ga.w)),
                         fmaxf(fmaxf(gb.x, gb.y), fmaxf(gb.z, gb.w)));
        #pragma unroll
        for (int o = 16; o > 0; o >>= 1) {
            mr = fmaxf(mr, __shfl_xor_sync(0xffffffffu, mr, o));
            mg = fmaxf(mg, __shfl_xor_sync(0xffffffffu, mg, o));
        }

        float sr = __expf(ra.x - mr) + __expf(ra.y - mr) + __expf(ra.z - mr) + __expf(ra.w - mr)
                 + __expf(rb.x - mr) + __expf(rb.y - mr) + __expf(rb.z - mr) + __expf(rb.w - mr);
        float sg = __expf(ga.x - mg) + __expf(ga.y - mg) + __expf(ga.z - mg) + __expf(ga.w - mg)
                 + __expf(gb.x - mg) + __expf(gb.y - mg) + __expf(gb.z - mg) + __expf(gb.w - mg);
        #pragma unroll
        for (int o = 16; o > 0; o >>= 1) {
            sr += __shfl_xor_sync(0xffffffffu, sr, o);
            sg += __shfl_xor_sync(0xffffffffu, sg, o);
        }

        if (lane == 0) {
            const float xr = __ldg(row + group);
            const float xg = __ldg(grp + child);
            loss = (mr + __logf(sr) - xr) + (mg + __logf(sg) - xg);
        }
    }
    if (lane == 0) sh_warp[wid] = loss;
    __syncthreads();

    // Warp 0 sums the 8 warp losses, publishes block partial, bumps counter.
    if (wid == 0) {
        float s = (lane < 8) ? sh_warp[lane] : 0.0f;
        #pragma unroll
        for (int o = 4; o > 0; o >>= 1) s += __shfl_xor_sync(0xffffffffu, s, o);
        if (lane == 0) {
            g_blockpart[blockIdx.x] = s;
            __threadfence();
            // atomicInc wraps to 0 when old == nblocks-1 -> self-reset for graph replay
            unsigned prev = atomicInc(&g_count, (unsigned)nblocks - 1u);
            sh_last = (prev == (unsigned)nblocks - 1u);
        }
    }
    __syncthreads();

    // Last block performs the deterministic final reduction.
    if (sh_last) {
        __shared__ float sh[256];
        float s = 0.0f;
        for (int i = threadIdx.x; i < nblocks; i += 256) s += g_blockpart[i];
        sh[threadIdx.x] = s;
        __syncthreads();
        #pragma unroll
        for (int o = 128; o > 0; o >>= 1) {
            if (threadIdx.x < o) sh[threadIdx.x] += sh[threadIdx.x + o];
            __syncthreads();
        }
        if (threadIdx.x == 0) out[0] = sh[0] / (float)Bn;
    }
}

extern "C" void kernel_launch(void* const* d_in, const int* in_sizes, int n_in,
                              void* d_out, int out_size)
{
    const float* pred = (const float*)d_in[0];
    const int* tgt = (const int*)d_in[1];
    int Bn = in_sizes[1];
    int nblocks = (Bn + 7) / 8;
    if (nblocks > MAXBLOCKS) nblocks = MAXBLOCKS;   // Bn <= 8192 by construction

    hsm_fused_kernel<<<nblocks, 256>>>(pred, tgt, (float*)d_out, Bn, nblocks);
}